// round 1
// baseline (speedup 1.0000x reference)
#include <cuda_runtime.h>

// MaxPool3d k=2 s=2 over fp32 [B=2, C=32, D=128, H=128, W=128] -> [2,32,64,64,64]
// Each thread: 2 outputs along W. Reads 4x float4 (two h-rows x two d-slices),
// writes 1x float2. Fully coalesced: warp covers one full 128-wide input row.

#define W_IN   128
#define HW_IN  (128 * 128)
#define DHW_IN (128 * 128 * 128)
#define W_OUT  64
#define HW_OUT (64 * 64)
#define DHW_OUT (64 * 64 * 64)

__global__ void __launch_bounds__(256) maxpool3d_k2s2_kernel(
    const float* __restrict__ in, float* __restrict__ out, int n_pairs)
{
    int tid = blockIdx.x * blockDim.x + threadIdx.x;
    if (tid >= n_pairs) return;

    // Decompose: tid -> (bc, d, h, wp) with wp in [0,32) covering 2 outputs.
    int wp = tid & 31;
    int t1 = tid >> 5;
    int h  = t1 & 63;
    int t2 = t1 >> 6;
    int d  = t2 & 63;
    int bc = t2 >> 6;           // 0..63 (B*C)

    // Input base: element offset of (bc, 2d, 2h, 4*wp)
    const float4* base = reinterpret_cast<const float4*>(
        in + (size_t)bc * DHW_IN + (size_t)(2 * d) * HW_IN + (size_t)(2 * h) * W_IN) + wp;

    float4 a0 = __ldg(base);                          // (2d,   2h  )
    float4 a1 = __ldg(base + (W_IN / 4));             // (2d,   2h+1)
    float4 a2 = __ldg(base + (HW_IN / 4));            // (2d+1, 2h  )
    float4 a3 = __ldg(base + (HW_IN / 4 + W_IN / 4)); // (2d+1, 2h+1)

    float m0 = fmaxf(fmaxf(fmaxf(a0.x, a0.y), fmaxf(a1.x, a1.y)),
                     fmaxf(fmaxf(a2.x, a2.y), fmaxf(a3.x, a3.y)));
    float m1 = fmaxf(fmaxf(fmaxf(a0.z, a0.w), fmaxf(a1.z, a1.w)),
                     fmaxf(fmaxf(a2.z, a2.w), fmaxf(a3.z, a3.w)));

    float2* op = reinterpret_cast<float2*>(
        out + (size_t)bc * DHW_OUT + (size_t)d * HW_OUT + (size_t)h * W_OUT) + wp;
    *op = make_float2(m0, m1);
}

extern "C" void kernel_launch(void* const* d_in, const int* in_sizes, int n_in,
                              void* d_out, int out_size)
{
    const float* in = (const float*)d_in[0];
    float* out = (float*)d_out;
    // out_size = 2*32*64*64*64 = 16,777,216 ; each thread writes 2 outputs.
    int n_pairs = out_size / 2;               // 8,388,608
    int threads = 256;
    int blocks = (n_pairs + threads - 1) / threads;
    maxpool3d_k2s2_kernel<<<blocks, threads>>>(in, out, n_pairs);
}